// round 15
// baseline (speedup 1.0000x reference)
#include <cuda_runtime.h>
#include <cuda_bf16.h>
#include <cstdint>

#define DI __device__ __forceinline__

// ------------------------------------------------------------------
// Problem dims (fixed by setup_inputs): N=8192 tokens, D=2048, H=8192
// ------------------------------------------------------------------
#define MAXN 8192
#define MAXD 2048
#define MAXH 8192

// ---------------- static device scratch (no allocations allowed) ----
__device__ __align__(256) __nv_bfloat16 g_X1q[(size_t)MAXN * MAXD];   // 32 MB
__device__ __align__(256) __nv_bfloat16 g_W1q[(size_t)MAXH * MAXD];   // 32 MB
__device__ __align__(256) __nv_bfloat16 g_X2q[(size_t)MAXN * MAXH];   // 128 MB
__device__ __align__(256) __nv_bfloat16 g_W2q[(size_t)MAXD * MAXH];   // 32 MB
__device__ __align__(256) float         g_X2 [(size_t)MAXN * MAXH];   // 256 MB (fp32 gelu out)
__device__ float    g_sX1[MAXN];
__device__ unsigned g_sX2bits[MAXN];  // row absmax of gelu(X2), float bits (epilogue-fused)
__device__ unsigned g_absW1bits;      // zero-init; atomicMax idempotent across replays
__device__ unsigned g_absW2bits;

// ------------------------------------------------------------------
// PTX helpers (base sm_103 ISA: cp.async / ldmatrix / mma.sync / mbarrier)
// ------------------------------------------------------------------
DI uint32_t smem_u32(const void* p) {
    uint32_t a;
    asm("{ .reg .u64 t; cvta.to.shared.u64 t, %1; cvt.u32.u64 %0, t; }" : "=r"(a) : "l"(p));
    return a;
}

DI void cp16(uint32_t s, const void* g) {
    asm volatile("cp.async.cg.shared.global [%0], [%1], 16;" :: "r"(s), "l"(g) : "memory");
}

DI void mbar_init(uint32_t a, uint32_t cnt) {
    asm volatile("mbarrier.init.shared.b64 [%0], %1;" :: "r"(a), "r"(cnt) : "memory");
}
DI void mbar_arrive(uint32_t a) {
    asm volatile("mbarrier.arrive.shared.b64 _, [%0];" :: "r"(a) : "memory");
}
DI void cp_async_mbar_arrive_noinc(uint32_t a) {
    asm volatile("cp.async.mbarrier.arrive.noinc.shared::cta.b64 [%0];" :: "r"(a) : "memory");
}
DI void mbar_wait(uint32_t mbar, uint32_t parity) {
    asm volatile(
        "{\n\t"
        ".reg .pred P1;\n\t"
        "LAB_WAIT_%=:\n\t"
        "mbarrier.try_wait.parity.shared.b64 P1, [%0], %1;\n\t"
        "@P1 bra.uni LAB_DONE_%=;\n\t"
        "bra.uni LAB_WAIT_%=;\n\t"
        "LAB_DONE_%=:\n\t"
        "}"
        :: "r"(mbar), "r"(parity) : "memory");
}

DI void ldsm4(uint32_t& r0, uint32_t& r1, uint32_t& r2, uint32_t& r3, uint32_t addr) {
    asm volatile("ldmatrix.sync.aligned.m8n8.x4.shared.b16 {%0,%1,%2,%3}, [%4];"
                 : "=r"(r0), "=r"(r1), "=r"(r2), "=r"(r3) : "r"(addr));
}

// bf16 HMMA, fp32 accumulate (exact for small-int inputs)
DI void mma_bf16(float* c, const uint32_t* a, const uint32_t* b) {
    asm volatile(
        "mma.sync.aligned.m16n8k16.row.col.f32.bf16.bf16.f32 "
        "{%0,%1,%2,%3},{%4,%5,%6,%7},{%8,%9},{%0,%1,%2,%3};"
        : "+f"(c[0]), "+f"(c[1]), "+f"(c[2]), "+f"(c[3])
        : "r"(a[0]), "r"(a[1]), "r"(a[2]), "r"(a[3]), "r"(b[0]), "r"(b[1]));
}

DI float gelu_tanh(float x) {
    float x3 = x * x * x;
    return 0.5f * x * (1.0f + tanhf(0.7978845608028654f * (x + 0.044715f * x3)));
}

DI uint32_t pack_bf16(float a, float b) {
    __nv_bfloat162 h = __floats2bfloat162_rn(a, b);
    return *reinterpret_cast<uint32_t*>(&h);
}

// ------------------------------------------------------------------
// Quantization kernels (int8 lattice stored as bf16 — exact)
// ------------------------------------------------------------------
__global__ void k_absmax(const float* __restrict__ w, long long n4, unsigned* out) {
    const float4* w4 = (const float4*)w;
    float m = 0.f;
    long long stride = (long long)gridDim.x * blockDim.x;
    for (long long i = (long long)blockIdx.x * blockDim.x + threadIdx.x; i < n4; i += stride) {
        float4 v = w4[i];
        m = fmaxf(m, fmaxf(fmaxf(fabsf(v.x), fabsf(v.y)), fmaxf(fabsf(v.z), fabsf(v.w))));
    }
#pragma unroll
    for (int o = 16; o; o >>= 1) m = fmaxf(m, __shfl_xor_sync(0xffffffffu, m, o));
    __shared__ float red[32];
    int lane = threadIdx.x & 31, wr = threadIdx.x >> 5;
    if (lane == 0) red[wr] = m;
    __syncthreads();
    if (wr == 0) {
        m = (lane < (int)(blockDim.x >> 5)) ? red[lane] : 0.f;
#pragma unroll
        for (int o = 16; o; o >>= 1) m = fmaxf(m, __shfl_xor_sync(0xffffffffu, m, o));
        if (lane == 0) atomicMax(out, __float_as_uint(m));
    }
}

__global__ void k_quant_global(const float* __restrict__ w, __nv_bfloat16* __restrict__ q,
                               const unsigned* __restrict__ bits, long long n4) {
    float inv = 127.0f / __uint_as_float(*bits);
    const float4* w4 = (const float4*)w;
    uint2* q4 = (uint2*)q;
    long long stride = (long long)gridDim.x * blockDim.x;
    for (long long i = (long long)blockIdx.x * blockDim.x + threadIdx.x; i < n4; i += stride) {
        float4 v = w4[i];
        float a = fmaxf(-127.f, fminf(127.f, rintf(v.x * inv)));
        float b = fmaxf(-127.f, fminf(127.f, rintf(v.y * inv)));
        float c = fmaxf(-127.f, fminf(127.f, rintf(v.z * inv)));
        float d = fmaxf(-127.f, fminf(127.f, rintf(v.w * inv)));
        q4[i] = make_uint2(pack_bf16(a, b), pack_bf16(c, d));
    }
}

// rowwise quant with smem row cache: single global read (cols <= 2048)
__global__ void k_quant_rows(const float* __restrict__ x, __nv_bfloat16* __restrict__ q,
                             float* __restrict__ s, int cols) {
    __shared__ float4 rowbuf[512];        // up to 2048 floats
    long long row = blockIdx.x;
    const float4* xr = (const float4*)(x + row * (long long)cols);
    const int n4 = cols >> 2;
    float m = 0.f;
    for (int c = threadIdx.x; c < n4; c += blockDim.x) {
        float4 v = xr[c];
        rowbuf[c] = v;
        m = fmaxf(m, fmaxf(fmaxf(fabsf(v.x), fabsf(v.y)), fmaxf(fabsf(v.z), fabsf(v.w))));
    }
#pragma unroll
    for (int o = 16; o; o >>= 1) m = fmaxf(m, __shfl_xor_sync(0xffffffffu, m, o));
    __shared__ float red[8];
    __shared__ float smax;
    int lane = threadIdx.x & 31, wr = threadIdx.x >> 5;
    if (lane == 0) red[wr] = m;
    __syncthreads();
    if (threadIdx.x == 0) {
        float t = red[0];
#pragma unroll
        for (int i = 1; i < 8; i++) t = fmaxf(t, red[i]);
        smax = t;
        s[row] = t;
    }
    __syncthreads();
    float inv = 127.f / smax;
    uint2* qr = (uint2*)(q + row * (long long)cols);
    for (int c = threadIdx.x; c < n4; c += blockDim.x) {
        float4 v = rowbuf[c];
        float a = fmaxf(-127.f, fminf(127.f, rintf(v.x * inv)));
        float b = fmaxf(-127.f, fminf(127.f, rintf(v.y * inv)));
        float cc = fmaxf(-127.f, fminf(127.f, rintf(v.z * inv)));
        float d = fmaxf(-127.f, fminf(127.f, rintf(v.w * inv)));
        qr[c] = make_uint2(pack_bf16(a, b), pack_bf16(cc, d));
    }
}

// single-pass rowwise quant with precomputed scale (used for X2)
__global__ void k_quant_scaled(const float* __restrict__ x, __nv_bfloat16* __restrict__ q,
                               const unsigned* __restrict__ sbits, int cols) {
    long long row = blockIdx.x;
    float inv = 127.f / __uint_as_float(sbits[row]);
    const float4* xr = (const float4*)(x + row * (long long)cols);
    uint2* qr = (uint2*)(q + row * (long long)cols);
    const int n4 = cols >> 2;
    for (int c = threadIdx.x; c < n4; c += blockDim.x) {
        float4 v = xr[c];
        float a = fmaxf(-127.f, fminf(127.f, rintf(v.x * inv)));
        float b = fmaxf(-127.f, fminf(127.f, rintf(v.y * inv)));
        float cc = fmaxf(-127.f, fminf(127.f, rintf(v.z * inv)));
        float d = fmaxf(-127.f, fminf(127.f, rintf(v.w * inv)));
        qr[c] = make_uint2(pack_bf16(a, b), pack_bf16(cc, d));
    }
}

// ------------------------------------------------------------------
// Warp-specialized bf16 HMMA GEMM: C[m,n] = sum_k A[m,k]*B[n,k]
// 5 warps: warps 0-3 = consumers (2x2 grid, warp tile 64x64),
//          warp 4   = producer (all cp.async).
// 3-stage ring, mbarrier full/empty pairs. NO __syncthreads and NO
// cp.async in the consumer mainloop. 2 CTA/SM.
// Swizzle: 16B chunk c of row r at r*128 + ((c ^ (r&7))<<4); XOR-linear in k.
// GELU: epilogue also reduces per-row |gelu| max into rowAbsOut.
// ------------------------------------------------------------------
#define BMT 128
#define BNT 128
#define BKE 64                            // k elements per stage (128 bytes)
#define STAGES 3
#define A_BYTES (BMT * 128)               // 16384
#define B_BYTES (BNT * 128)               // 16384
#define STAGE_BYTES (A_BYTES + B_BYTES)   // 32768
#define TILE0 1024                        // tiles start (mbarriers below)
#define GEMM_SMEM (TILE0 + STAGES * STAGE_BYTES)  // 99328

DI uint32_t swz(int row, int chunk) {
    return (uint32_t)(row * 128 + ((chunk ^ (row & 7)) << 4));
}

template <int GELU>
__global__ void __launch_bounds__(160, 2)
k_gemm(const __nv_bfloat16* __restrict__ A, const __nv_bfloat16* __restrict__ B,
       const float* __restrict__ rowScale, const unsigned* __restrict__ wBits,
       const float* __restrict__ bias, float* __restrict__ out,
       unsigned* __restrict__ rowAbsOut, int K, int Ncols) {
    constexpr int MI = 4;                 // m16 tiles per warp (64 rows)
    constexpr int JP = 4;                 // n16 pairs per warp (64 cols)

    extern __shared__ char smem[];
    const uint32_t sb = smem_u32(smem);
    const uint32_t mbF = sb;              // full[0..2] at +0,+8,+16
    const uint32_t mbE = sb + 24;         // empty[0..2] at +24,+32,+40
    const uint32_t t0 = sb + TILE0;
    const int tid  = threadIdx.x;
    const int lane = tid & 31;
    const int wid  = tid >> 5;

    const int m0 = blockIdx.y * BMT;
    const int n0 = blockIdx.x * BNT;
    const __nv_bfloat16* Ab = A + (long long)m0 * K;
    const __nv_bfloat16* Bb = B + (long long)n0 * K;
    const int nchunks = K / BKE;

    if (tid == 0) {
#pragma unroll
        for (int s = 0; s < STAGES; s++) {
            mbar_init(mbF + s * 8, 32);    // producer warp, noinc async arrives
            mbar_init(mbE + s * 8, 128);   // 4 consumer warps arrive
        }
    }
    __syncthreads();                       // only barrier in the kernel

    if (wid == 4) {
        // ---------------- producer warp ----------------
        int pst = 0, pph = 1;              // first 3 empty-waits pass immediately
        for (int c = 0; c < nchunks; c++) {
            mbar_wait(mbE + pst * 8, (uint32_t)pph);
            const uint32_t base = t0 + pst * STAGE_BYTES;
            const __nv_bfloat16* gA = Ab + (long long)c * BKE;
            const __nv_bfloat16* gB = Bb + (long long)c * BKE;
#pragma unroll 8
            for (int i = 0; i < 32; i++) {
                int idx = lane + i * 32;
                int r = idx >> 3, ch = idx & 7;
                cp16(base + swz(r, ch), gA + (long long)r * K + ch * 8);
            }
#pragma unroll 8
            for (int i = 0; i < 32; i++) {
                int idx = lane + i * 32;
                int r = idx >> 3, ch = idx & 7;
                cp16(base + A_BYTES + swz(r, ch), gB + (long long)r * K + ch * 8);
            }
            cp_async_mbar_arrive_noinc(mbF + pst * 8);
            if (++pst == STAGES) { pst = 0; pph ^= 1; }
        }
        return;                            // producer done
    }

    // ---------------- consumer warps (0..3) ----------------
    const int wm = wid & 1;                // 2 warps along M
    const int wn = wid >> 1;               // 2 warps along N

    float acc[MI][JP * 2][4];
#pragma unroll
    for (int i = 0; i < MI; i++)
#pragma unroll
        for (int j = 0; j < JP * 2; j++)
#pragma unroll
            for (int r = 0; r < 4; r++) acc[i][j][r] = 0.f;

    const int l8  = lane & 7;
    const int lhi = lane >> 3;             // 0..3
    uint32_t aOff0[MI], bOff0[JP];
#pragma unroll
    for (int i = 0; i < MI; i++) {
        int mrow = wm * 64 + i * 16 + ((lhi & 1) << 3) + l8;
        aOff0[i] = swz(mrow, lhi >> 1);
    }
#pragma unroll
    for (int jp = 0; jp < JP; jp++) {
        int nrow = wn * 64 + jp * 16 + ((lhi >> 1) << 3) + l8;
        bOff0[jp] = (uint32_t)A_BYTES + swz(nrow, lhi & 1);
    }

    uint32_t af[2][MI][4];                 // A frags double-buffered per k16 step
    uint32_t bb[2][4];                     // B frags double-buffered per jp

    int cst = 0, cph = 0;
    for (int c = 0; c < nchunks; c++) {
        mbar_wait(mbF + cst * 8, (uint32_t)cph);
        const uint32_t base = t0 + cst * STAGE_BYTES;

        // initial fragments for ks=0
#pragma unroll
        for (int i = 0; i < MI; i++)
            ldsm4(af[0][i][0], af[0][i][1], af[0][i][2], af[0][i][3], base + aOff0[i]);
        ldsm4(bb[0][0], bb[0][1], bb[0][2], bb[0][3], base + bOff0[0]);

#pragma unroll
        for (int ks = 0; ks < 4; ks++) {
            const int cur = ks & 1;
            if (ks < 3) {                  // prefetch next k-step A frags
                const uint32_t kx = (uint32_t)((ks + 1) << 5);
#pragma unroll
                for (int i = 0; i < MI; i++)
                    ldsm4(af[cur ^ 1][i][0], af[cur ^ 1][i][1],
                          af[cur ^ 1][i][2], af[cur ^ 1][i][3], base + (aOff0[i] ^ kx));
            }
            const uint32_t kxc = (uint32_t)(ks << 5);
#pragma unroll
            for (int jp = 0; jp < JP; jp++) {
                const int bc = jp & 1;
                if (jp < 3) {              // prefetch next jp's B
                    ldsm4(bb[bc ^ 1][0], bb[bc ^ 1][1], bb[bc ^ 1][2], bb[bc ^ 1][3],
                          base + (bOff0[jp + 1] ^ kxc));
                } else if (ks < 3) {       // prefetch (ks+1, jp=0)
                    ldsm4(bb[bc ^ 1][0], bb[bc ^ 1][1], bb[bc ^ 1][2], bb[bc ^ 1][3],
                          base + (bOff0[0] ^ (uint32_t)((ks + 1) << 5)));
                }
#pragma unroll
                for (int i = 0; i < MI; i++) {
                    mma_bf16(acc[i][jp * 2 + 0], af[cur][i], bb[bc]);
                    mma_bf16(acc[i][jp * 2 + 1], af[cur][i], bb[bc] + 2);
                }
            }
        }
        mbar_arrive(mbE + cst * 8);        // stage reusable
        if (++cst == STAGES) { cst = 0; cph ^= 1; }
    }

    // ---------------- epilogue: dequant + bias (+gelu, +row absmax) ----
    const float sW = __uint_as_float(*wBits);
    const float fg = sW * (1.0f / 16129.0f);      // /(127*127)
    const int qrow = lane >> 2;
    const int w    = lane & 3;

#pragma unroll
    for (int i = 0; i < MI; i++) {
        const int r0 = m0 + wm * 64 + i * 16 + qrow;
        const int r1 = r0 + 8;
        const float f0 = rowScale[r0] * fg;
        const float f1 = rowScale[r1] * fg;
        float* o0 = out + (long long)r0 * Ncols;
        float* o1 = out + (long long)r1 * Ncols;
        float rm0 = 0.f, rm1 = 0.f;
#pragma unroll
        for (int j = 0; j < JP * 2; j++) {
            const int col = n0 + wn * 64 + j * 8 + w * 2;
            const float b0 = bias[col], b1 = bias[col + 1];
            float2 v0, v1;
            v0.x = acc[i][j][0] * f0 + b0;
            v0.y = acc[i][j][1] * f0 + b1;
            v1.x = acc[i][j][2] * f1 + b0;
            v1.y = acc[i][j][3] * f1 + b1;
            if (GELU) {
                v0.x = gelu_tanh(v0.x); v0.y = gelu_tanh(v0.y);
                v1.x = gelu_tanh(v1.x); v1.y = gelu_tanh(v1.y);
                rm0 = fmaxf(rm0, fmaxf(fabsf(v0.x), fabsf(v0.y)));
                rm1 = fmaxf(rm1, fmaxf(fabsf(v1.x), fabsf(v1.y)));
            }
            *reinterpret_cast<float2*>(o0 + col) = v0;
            *reinterpret_cast<float2*>(o1 + col) = v1;
        }
        if (GELU) {
            rm0 = fmaxf(rm0, __shfl_xor_sync(0xffffffffu, rm0, 1));
            rm0 = fmaxf(rm0, __shfl_xor_sync(0xffffffffu, rm0, 2));
            rm1 = fmaxf(rm1, __shfl_xor_sync(0xffffffffu, rm1, 1));
            rm1 = fmaxf(rm1, __shfl_xor_sync(0xffffffffu, rm1, 2));
            if (w == 0) {
                atomicMax(rowAbsOut + r0, __float_as_uint(rm0));
                atomicMax(rowAbsOut + r1, __float_as_uint(rm1));
            }
        }
    }
}

// ------------------------------------------------------------------
// Launch — quant_rows(x) and W2 chain forked onto a second stream
// ------------------------------------------------------------------
extern "C" void kernel_launch(void* const* d_in, const int* in_sizes, int n_in,
                              void* d_out, int out_size) {
    const float* x  = (const float*)d_in[0];
    const float* W1 = (const float*)d_in[1];
    const float* B1 = (const float*)d_in[2];
    const float* W2 = (const float*)d_in[3];
    const float* B2 = (const float*)d_in[4];
    const int H = in_sizes[2];            // 8192
    const int D = in_sizes[4];            // 2048
    const int N = in_sizes[0] / D;        // 8192
    float* out = (float*)d_out;

    void *pX1q = 0, *pW1q = 0, *pX2q = 0, *pW2q = 0, *pX2 = 0,
         *psX1 = 0, *psX2 = 0, *pa1 = 0, *pa2 = 0;
    cudaGetSymbolAddress(&pX1q, g_X1q);
    cudaGetSymbolAddress(&pW1q, g_W1q);
    cudaGetSymbolAddress(&pX2q, g_X2q);
    cudaGetSymbolAddress(&pW2q, g_W2q);
    cudaGetSymbolAddress(&pX2,  g_X2);
    cudaGetSymbolAddress(&psX1, g_sX1);
    cudaGetSymbolAddress(&psX2, g_sX2bits);
    cudaGetSymbolAddress(&pa1,  g_absW1bits);
    cudaGetSymbolAddress(&pa2,  g_absW2bits);

    cudaFuncSetAttribute((const void*)k_gemm<1>, cudaFuncAttributeMaxDynamicSharedMemorySize, GEMM_SMEM);
    cudaFuncSetAttribute((const void*)k_gemm<0>, cudaFuncAttributeMaxDynamicSharedMemorySize, GEMM_SMEM);

    // One-time stream/event creation (host resources, not device memory).
    static cudaStream_t s2 = nullptr;
    static cudaEvent_t evF0 = nullptr, evJ0 = nullptr, evF1 = nullptr, evJ1 = nullptr;
    if (!s2) {
        cudaStreamCreateWithFlags(&s2, cudaStreamNonBlocking);
        cudaEventCreateWithFlags(&evF0, cudaEventDisableTiming);
        cudaEventCreateWithFlags(&evJ0, cudaEventDisableTiming);
        cudaEventCreateWithFlags(&evF1, cudaEventDisableTiming);
        cudaEventCreateWithFlags(&evJ1, cudaEventDisableTiming);
    }

    // fork 0: quant_rows(x) on s2 parallel with the W1 chain
    cudaEventRecord(evF0, 0);
    cudaStreamWaitEvent(s2, evF0, 0);
    k_quant_rows<<<N, 256, 0, s2>>>(x, (__nv_bfloat16*)pX1q, (float*)psX1, D);
    cudaEventRecord(evJ0, s2);

    k_absmax<<<1024, 256>>>(W1, ((long long)H * D) >> 2, (unsigned*)pa1);
    k_quant_global<<<2048, 256>>>(W1, (__nv_bfloat16*)pW1q, (const unsigned*)pa1,
                                  ((long long)H * D) >> 2);
    cudaStreamWaitEvent(0, evJ0, 0);

    // fork 1: W2 quant chain on s2 concurrent with GEMM1
    cudaEventRecord(evF1, 0);
    cudaStreamWaitEvent(s2, evF1, 0);
    k_absmax<<<1024, 256, 0, s2>>>(W2, ((long long)D * H) >> 2, (unsigned*)pa2);
    k_quant_global<<<2048, 256, 0, s2>>>(W2, (__nv_bfloat16*)pW2q, (const unsigned*)pa2,
                                         ((long long)D * H) >> 2);
    cudaEventRecord(evJ1, s2);

    dim3 g1(H / BNT, N / BMT);   // (64, 64)
    k_gemm<1><<<g1, 160, GEMM_SMEM>>>(
        (const __nv_bfloat16*)pX1q, (const __nv_bfloat16*)pW1q,
        (const float*)psX1, (const unsigned*)pa1, B1, (float*)pX2,
        (unsigned*)psX2, D, H);

    k_quant_scaled<<<N, 256>>>((const float*)pX2, (__nv_bfloat16*)pX2q,
                               (const unsigned*)psX2, H);

    cudaStreamWaitEvent(0, evJ1, 0);

    dim3 g2(D / BNT, N / BMT);   // (16, 64)
    k_gemm<0><<<g2, 160, GEMM_SMEM>>>(
        (const __nv_bfloat16*)pX2q, (const __nv_bfloat16*)pW2q,
        (const float*)psX2, (const unsigned*)pa2, B2, out,
        nullptr, H, D);
}

// round 16
// speedup vs baseline: 1.4207x; 1.4207x over previous
#include <cuda_runtime.h>
#include <cuda_bf16.h>
#include <cstdint>

#define DI __device__ __forceinline__

// ------------------------------------------------------------------
// Problem dims (fixed by setup_inputs): N=8192 tokens, D=2048, H=8192
// ------------------------------------------------------------------
#define MAXN 8192
#define MAXD 2048
#define MAXH 8192

// ---------------- static device scratch (no allocations allowed) ----
__device__ __align__(256) __nv_bfloat16 g_X1q[(size_t)MAXN * MAXD];   // 32 MB
__device__ __align__(256) __nv_bfloat16 g_W1q[(size_t)MAXH * MAXD];   // 32 MB
__device__ __align__(256) __nv_bfloat16 g_X2q[(size_t)MAXN * MAXH];   // 128 MB
__device__ __align__(256) __nv_bfloat16 g_W2q[(size_t)MAXD * MAXH];   // 32 MB
__device__ __align__(256) float         g_X2 [(size_t)MAXN * MAXH];   // 256 MB (fp32 gelu out)
__device__ float    g_sX1[MAXN];
__device__ unsigned g_sX2bits[MAXN];  // row absmax of gelu(X2), float bits (epilogue-fused)
__device__ unsigned g_absW1bits;      // zero-init; atomicMax idempotent across replays
__device__ unsigned g_absW2bits;

// ------------------------------------------------------------------
// PTX helpers (base sm_103 ISA only: cp.async / ldmatrix / mma.sync)
// ------------------------------------------------------------------
DI uint32_t smem_u32(const void* p) {
    uint32_t a;
    asm("{ .reg .u64 t; cvta.to.shared.u64 t, %1; cvt.u32.u64 %0, t; }" : "=r"(a) : "l"(p));
    return a;
}

DI void cp16(uint32_t s, const void* g) {
    asm volatile("cp.async.cg.shared.global [%0], [%1], 16;" :: "r"(s), "l"(g) : "memory");
}
DI void cp_commit() { asm volatile("cp.async.commit_group;" ::: "memory"); }
template <int N>
DI void cp_wait() { asm volatile("cp.async.wait_group %0;" :: "n"(N) : "memory"); }

DI void ldsm4(uint32_t& r0, uint32_t& r1, uint32_t& r2, uint32_t& r3, uint32_t addr) {
    asm volatile("ldmatrix.sync.aligned.m8n8.x4.shared.b16 {%0,%1,%2,%3}, [%4];"
                 : "=r"(r0), "=r"(r1), "=r"(r2), "=r"(r3) : "r"(addr));
}

// bf16 HMMA, fp32 accumulate (exact for small-int inputs)
DI void mma_bf16(float* c, const uint32_t* a, const uint32_t* b) {
    asm volatile(
        "mma.sync.aligned.m16n8k16.row.col.f32.bf16.bf16.f32 "
        "{%0,%1,%2,%3},{%4,%5,%6,%7},{%8,%9},{%0,%1,%2,%3};"
        : "+f"(c[0]), "+f"(c[1]), "+f"(c[2]), "+f"(c[3])
        : "r"(a[0]), "r"(a[1]), "r"(a[2]), "r"(a[3]), "r"(b[0]), "r"(b[1]));
}

DI float gelu_tanh(float x) {
    float x3 = x * x * x;
    return 0.5f * x * (1.0f + tanhf(0.7978845608028654f * (x + 0.044715f * x3)));
}

DI uint32_t pack_bf16(float a, float b) {
    __nv_bfloat162 h = __floats2bfloat162_rn(a, b);
    return *reinterpret_cast<uint32_t*>(&h);
}

// ------------------------------------------------------------------
// Quantization kernels (int8 lattice stored as bf16 — exact)
// ------------------------------------------------------------------
__global__ void k_absmax(const float* __restrict__ w, long long n4, unsigned* out) {
    const float4* w4 = (const float4*)w;
    float m = 0.f;
    long long stride = (long long)gridDim.x * blockDim.x;
    for (long long i = (long long)blockIdx.x * blockDim.x + threadIdx.x; i < n4; i += stride) {
        float4 v = w4[i];
        m = fmaxf(m, fmaxf(fmaxf(fabsf(v.x), fabsf(v.y)), fmaxf(fabsf(v.z), fabsf(v.w))));
    }
#pragma unroll
    for (int o = 16; o; o >>= 1) m = fmaxf(m, __shfl_xor_sync(0xffffffffu, m, o));
    __shared__ float red[32];
    int lane = threadIdx.x & 31, wr = threadIdx.x >> 5;
    if (lane == 0) red[wr] = m;
    __syncthreads();
    if (wr == 0) {
        m = (lane < (int)(blockDim.x >> 5)) ? red[lane] : 0.f;
#pragma unroll
        for (int o = 16; o; o >>= 1) m = fmaxf(m, __shfl_xor_sync(0xffffffffu, m, o));
        if (lane == 0) atomicMax(out, __float_as_uint(m));
    }
}

__global__ void k_quant_global(const float* __restrict__ w, __nv_bfloat16* __restrict__ q,
                               const unsigned* __restrict__ bits, long long n4) {
    float inv = 127.0f / __uint_as_float(*bits);
    const float4* w4 = (const float4*)w;
    uint2* q4 = (uint2*)q;
    long long stride = (long long)gridDim.x * blockDim.x;
    for (long long i = (long long)blockIdx.x * blockDim.x + threadIdx.x; i < n4; i += stride) {
        float4 v = w4[i];
        float a = fmaxf(-127.f, fminf(127.f, rintf(v.x * inv)));
        float b = fmaxf(-127.f, fminf(127.f, rintf(v.y * inv)));
        float c = fmaxf(-127.f, fminf(127.f, rintf(v.z * inv)));
        float d = fmaxf(-127.f, fminf(127.f, rintf(v.w * inv)));
        q4[i] = make_uint2(pack_bf16(a, b), pack_bf16(c, d));
    }
}

// rowwise quant with smem row cache: single global read (cols <= 2048)
__global__ void k_quant_rows(const float* __restrict__ x, __nv_bfloat16* __restrict__ q,
                             float* __restrict__ s, int cols) {
    __shared__ float4 rowbuf[512];        // up to 2048 floats
    long long row = blockIdx.x;
    const float4* xr = (const float4*)(x + row * (long long)cols);
    const int n4 = cols >> 2;
    float m = 0.f;
    for (int c = threadIdx.x; c < n4; c += blockDim.x) {
        float4 v = xr[c];
        rowbuf[c] = v;
        m = fmaxf(m, fmaxf(fmaxf(fabsf(v.x), fabsf(v.y)), fmaxf(fabsf(v.z), fabsf(v.w))));
    }
#pragma unroll
    for (int o = 16; o; o >>= 1) m = fmaxf(m, __shfl_xor_sync(0xffffffffu, m, o));
    __shared__ float red[8];
    __shared__ float smax;
    int lane = threadIdx.x & 31, wr = threadIdx.x >> 5;
    if (lane == 0) red[wr] = m;
    __syncthreads();
    if (threadIdx.x == 0) {
        float t = red[0];
#pragma unroll
        for (int i = 1; i < 8; i++) t = fmaxf(t, red[i]);
        smax = t;
        s[row] = t;
    }
    __syncthreads();
    float inv = 127.f / smax;
    uint2* qr = (uint2*)(q + row * (long long)cols);
    for (int c = threadIdx.x; c < n4; c += blockDim.x) {
        float4 v = rowbuf[c];
        float a = fmaxf(-127.f, fminf(127.f, rintf(v.x * inv)));
        float b = fmaxf(-127.f, fminf(127.f, rintf(v.y * inv)));
        float cc = fmaxf(-127.f, fminf(127.f, rintf(v.z * inv)));
        float d = fmaxf(-127.f, fminf(127.f, rintf(v.w * inv)));
        qr[c] = make_uint2(pack_bf16(a, b), pack_bf16(cc, d));
    }
}

// single-pass rowwise quant with precomputed scale (used for X2)
__global__ void k_quant_scaled(const float* __restrict__ x, __nv_bfloat16* __restrict__ q,
                               const unsigned* __restrict__ sbits, int cols) {
    long long row = blockIdx.x;
    float inv = 127.f / __uint_as_float(sbits[row]);
    const float4* xr = (const float4*)(x + row * (long long)cols);
    uint2* qr = (uint2*)(q + row * (long long)cols);
    const int n4 = cols >> 2;
    for (int c = threadIdx.x; c < n4; c += blockDim.x) {
        float4 v = xr[c];
        float a = fmaxf(-127.f, fminf(127.f, rintf(v.x * inv)));
        float b = fmaxf(-127.f, fminf(127.f, rintf(v.y * inv)));
        float cc = fmaxf(-127.f, fminf(127.f, rintf(v.z * inv)));
        float d = fmaxf(-127.f, fminf(127.f, rintf(v.w * inv)));
        qr[c] = make_uint2(pack_bf16(a, b), pack_bf16(cc, d));
    }
}

// ------------------------------------------------------------------
// bf16 HMMA GEMM (R10/R14 proven config): C[m,n] = sum_k A[m,k]*B[n,k]
// CTA tile 128x128, 4 warps (2x2), warp tile 64x64, 2 CTA/SM.
// K-chunk = 64 elements (128B rows), 3-stage cp.async pipeline,
// software-pipelined register fragments.
// GELU: epilogue also reduces per-row |gelu| max into rowAbsOut.
// ------------------------------------------------------------------
#define BMT 128
#define BNT 128
#define BKE 64                            // k elements per stage (128 bytes)
#define STAGES 3
#define A_BYTES (BMT * 128)               // 16384
#define B_BYTES (BNT * 128)               // 16384
#define STAGE_BYTES (A_BYTES + B_BYTES)   // 32768
#define GEMM_SMEM (STAGES * STAGE_BYTES)  // 98304

DI uint32_t swz(int row, int chunk) {
    return (uint32_t)(row * 128 + ((chunk ^ (row & 7)) << 4));
}

template <int ROWS, int THREADS>
DI void load_rows(uint32_t s, const __nv_bfloat16* g, int K, int tid) {
#pragma unroll
    for (int i = 0; i < (ROWS * 8) / THREADS; i++) {
        int idx = tid + i * THREADS;
        int r = idx >> 3, c = idx & 7;
        cp16(s + swz(r, c), g + (long long)r * K + c * 8);
    }
}

template <int GELU>
__global__ void __launch_bounds__(128, 2)
k_gemm(const __nv_bfloat16* __restrict__ A, const __nv_bfloat16* __restrict__ B,
       const float* __restrict__ rowScale, const unsigned* __restrict__ wBits,
       const float* __restrict__ bias, float* __restrict__ out,
       unsigned* __restrict__ rowAbsOut, int K, int Ncols) {
    constexpr int THREADS = 128;
    constexpr int MI = 4;                 // m16 tiles per warp (64 rows)
    constexpr int JP = 4;                 // n16 pairs per warp (64 cols)

    extern __shared__ char smem[];
    const uint32_t sb = smem_u32(smem);
    const int tid  = threadIdx.x;
    const int lane = tid & 31;
    const int wid  = tid >> 5;
    const int wm   = wid & 1;             // 2 warps along M
    const int wn   = wid >> 1;            // 2 warps along N

    const int m0 = blockIdx.y * BMT;
    const int n0 = blockIdx.x * BNT;
    const __nv_bfloat16* Ab = A + (long long)m0 * K;
    const __nv_bfloat16* Bb = B + (long long)n0 * K;
    const int nchunks = K / BKE;

    float acc[MI][JP * 2][4];
#pragma unroll
    for (int i = 0; i < MI; i++)
#pragma unroll
        for (int j = 0; j < JP * 2; j++)
#pragma unroll
            for (int r = 0; r < 4; r++) acc[i][j][r] = 0.f;

    // loop-invariant ldmatrix offsets at ks=0 (XOR with ks<<5 gives others)
    const int l8  = lane & 7;
    const int lhi = lane >> 3;            // 0..3
    uint32_t aOff0[MI], bOff0[JP];
#pragma unroll
    for (int i = 0; i < MI; i++) {
        int mrow = wm * 64 + i * 16 + ((lhi & 1) << 3) + l8;
        aOff0[i] = swz(mrow, lhi >> 1);
    }
#pragma unroll
    for (int jp = 0; jp < JP; jp++) {
        int nrow = wn * 64 + jp * 16 + ((lhi >> 1) << 3) + l8;
        bOff0[jp] = (uint32_t)A_BYTES + swz(nrow, lhi & 1);
    }

    // prologue: fill stages 0 and 1
#pragma unroll
    for (int s = 0; s < STAGES - 1; s++) {
        uint32_t st = sb + s * STAGE_BYTES;
        load_rows<BMT, THREADS>(st, Ab + s * BKE, K, tid);
        load_rows<BNT, THREADS>(st + A_BYTES, Bb + s * BKE, K, tid);
        cp_commit();
    }

    // double-buffered register fragments
    uint32_t af[2][MI][4], bf[2][JP][4];

    int stage = 0;                        // stage slot of chunk c
    for (int c = 0; c < nchunks; c++) {
        cp_wait<STAGES - 2>();            // chunk c resident
        __syncthreads();                  // everyone done reading chunk c-1

        const uint32_t base = sb + stage * STAGE_BYTES;

        // ks=0 fragment LDSMs first (start latency early) ...
#pragma unroll
        for (int i = 0; i < MI; i++)
            ldsm4(af[0][i][0], af[0][i][1], af[0][i][2], af[0][i][3], base + aOff0[i]);
#pragma unroll
        for (int jp = 0; jp < JP; jp++)
            ldsm4(bf[0][jp][0], bf[0][jp][1], bf[0][jp][2], bf[0][jp][3], base + bOff0[jp]);

        // ... then gmem prefetch of chunk c+2 fills the LDSM latency window
        const int nc = c + STAGES - 1;
        const int ls = (stage >= 1) ? stage - 1 : STAGES - 1;
        if (nc < nchunks) {
            uint32_t st = sb + ls * STAGE_BYTES;
            load_rows<BMT, THREADS>(st, Ab + (long long)nc * BKE, K, tid);
            load_rows<BNT, THREADS>(st + A_BYTES, Bb + (long long)nc * BKE, K, tid);
        }
        cp_commit();                      // uniform group accounting

#pragma unroll
        for (int ks = 0; ks < 4; ks++) {  // four k16 steps per 64-elem chunk
            const int cur = ks & 1;
            if (ks < 3) {                 // prefetch ks+1 frags BEFORE ks MMAs
                const uint32_t kx = (uint32_t)((ks + 1) << 5);
#pragma unroll
                for (int i = 0; i < MI; i++)
                    ldsm4(af[cur ^ 1][i][0], af[cur ^ 1][i][1],
                          af[cur ^ 1][i][2], af[cur ^ 1][i][3], base + (aOff0[i] ^ kx));
#pragma unroll
                for (int jp = 0; jp < JP; jp++)
                    ldsm4(bf[cur ^ 1][jp][0], bf[cur ^ 1][jp][1],
                          bf[cur ^ 1][jp][2], bf[cur ^ 1][jp][3], base + (bOff0[jp] ^ kx));
            }
#pragma unroll
            for (int jp = 0; jp < JP; jp++)
#pragma unroll
                for (int i = 0; i < MI; i++) {
                    mma_bf16(acc[i][jp * 2 + 0], af[cur][i], bf[cur][jp]);
                    mma_bf16(acc[i][jp * 2 + 1], af[cur][i], bf[cur][jp] + 2);
                }
        }
        stage = (stage + 1 == STAGES) ? 0 : stage + 1;
    }

    // ---------------- epilogue: dequant + bias (+gelu, +row absmax) ----
    const float sW = __uint_as_float(*wBits);
    const float fg = sW * (1.0f / 16129.0f);      // /(127*127)
    const int qrow = lane >> 2;
    const int w    = lane & 3;

#pragma unroll
    for (int i = 0; i < MI; i++) {
        const int r0 = m0 + wm * 64 + i * 16 + qrow;
        const int r1 = r0 + 8;
        const float f0 = rowScale[r0] * fg;
        const float f1 = rowScale[r1] * fg;
        float* o0 = out + (long long)r0 * Ncols;
        float* o1 = out + (long long)r1 * Ncols;
        float rm0 = 0.f, rm1 = 0.f;
#pragma unroll
        for (int j = 0; j < JP * 2; j++) {
            const int col = n0 + wn * 64 + j * 8 + w * 2;
            const float b0 = bias[col], b1 = bias[col + 1];
            float2 v0, v1;
            v0.x = acc[i][j][0] * f0 + b0;
            v0.y = acc[i][j][1] * f0 + b1;
            v1.x = acc[i][j][2] * f1 + b0;
            v1.y = acc[i][j][3] * f1 + b1;
            if (GELU) {
                v0.x = gelu_tanh(v0.x); v0.y = gelu_tanh(v0.y);
                v1.x = gelu_tanh(v1.x); v1.y = gelu_tanh(v1.y);
                rm0 = fmaxf(rm0, fmaxf(fabsf(v0.x), fabsf(v0.y)));
                rm1 = fmaxf(rm1, fmaxf(fabsf(v1.x), fabsf(v1.y)));
            }
            *reinterpret_cast<float2*>(o0 + col) = v0;
            *reinterpret_cast<float2*>(o1 + col) = v1;
        }
        if (GELU) {
            rm0 = fmaxf(rm0, __shfl_xor_sync(0xffffffffu, rm0, 1));
            rm0 = fmaxf(rm0, __shfl_xor_sync(0xffffffffu, rm0, 2));
            rm1 = fmaxf(rm1, __shfl_xor_sync(0xffffffffu, rm1, 1));
            rm1 = fmaxf(rm1, __shfl_xor_sync(0xffffffffu, rm1, 2));
            if (w == 0) {
                atomicMax(rowAbsOut + r0, __float_as_uint(rm0));
                atomicMax(rowAbsOut + r1, __float_as_uint(rm1));
            }
        }
    }
}

// ------------------------------------------------------------------
// Launch — quant_rows(x) and W2 chain forked onto a second stream
// ------------------------------------------------------------------
extern "C" void kernel_launch(void* const* d_in, const int* in_sizes, int n_in,
                              void* d_out, int out_size) {
    const float* x  = (const float*)d_in[0];
    const float* W1 = (const float*)d_in[1];
    const float* B1 = (const float*)d_in[2];
    const float* W2 = (const float*)d_in[3];
    const float* B2 = (const float*)d_in[4];
    const int H = in_sizes[2];            // 8192
    const int D = in_sizes[4];            // 2048
    const int N = in_sizes[0] / D;        // 8192
    float* out = (float*)d_out;

    void *pX1q = 0, *pW1q = 0, *pX2q = 0, *pW2q = 0, *pX2 = 0,
         *psX1 = 0, *psX2 = 0, *pa1 = 0, *pa2 = 0;
    cudaGetSymbolAddress(&pX1q, g_X1q);
    cudaGetSymbolAddress(&pW1q, g_W1q);
    cudaGetSymbolAddress(&pX2q, g_X2q);
    cudaGetSymbolAddress(&pW2q, g_W2q);
    cudaGetSymbolAddress(&pX2,  g_X2);
    cudaGetSymbolAddress(&psX1, g_sX1);
    cudaGetSymbolAddress(&psX2, g_sX2bits);
    cudaGetSymbolAddress(&pa1,  g_absW1bits);
    cudaGetSymbolAddress(&pa2,  g_absW2bits);

    cudaFuncSetAttribute((const void*)k_gemm<1>, cudaFuncAttributeMaxDynamicSharedMemorySize, GEMM_SMEM);
    cudaFuncSetAttribute((const void*)k_gemm<0>, cudaFuncAttributeMaxDynamicSharedMemorySize, GEMM_SMEM);

    // One-time stream/event creation (host resources, not device memory).
    static cudaStream_t s2 = nullptr;
    static cudaEvent_t evF0 = nullptr, evJ0 = nullptr, evF1 = nullptr, evJ1 = nullptr;
    if (!s2) {
        cudaStreamCreateWithFlags(&s2, cudaStreamNonBlocking);
        cudaEventCreateWithFlags(&evF0, cudaEventDisableTiming);
        cudaEventCreateWithFlags(&evJ0, cudaEventDisableTiming);
        cudaEventCreateWithFlags(&evF1, cudaEventDisableTiming);
        cudaEventCreateWithFlags(&evJ1, cudaEventDisableTiming);
    }

    // fork 0: quant_rows(x) on s2 parallel with the W1 quant chain
    cudaEventRecord(evF0, 0);
    cudaStreamWaitEvent(s2, evF0, 0);
    k_quant_rows<<<N, 256, 0, s2>>>(x, (__nv_bfloat16*)pX1q, (float*)psX1, D);
    cudaEventRecord(evJ0, s2);

    k_absmax<<<1024, 256>>>(W1, ((long long)H * D) >> 2, (unsigned*)pa1);
    k_quant_global<<<2048, 256>>>(W1, (__nv_bfloat16*)pW1q, (const unsigned*)pa1,
                                  ((long long)H * D) >> 2);
    cudaStreamWaitEvent(0, evJ0, 0);      // GEMM1 needs X1q + sX1

    // fork 1: W2 quant chain on s2 concurrent with GEMM1
    cudaEventRecord(evF1, 0);
    cudaStreamWaitEvent(s2, evF1, 0);
    k_absmax<<<1024, 256, 0, s2>>>(W2, ((long long)D * H) >> 2, (unsigned*)pa2);
    k_quant_global<<<2048, 256, 0, s2>>>(W2, (__nv_bfloat16*)pW2q, (const unsigned*)pa2,
                                         ((long long)D * H) >> 2);
    cudaEventRecord(evJ1, s2);

    dim3 g1(H / BNT, N / BMT);   // (64, 64)
    k_gemm<1><<<g1, 128, GEMM_SMEM>>>(
        (const __nv_bfloat16*)pX1q, (const __nv_bfloat16*)pW1q,
        (const float*)psX1, (const unsigned*)pa1, B1, (float*)pX2,
        (unsigned*)psX2, D, H);

    k_quant_scaled<<<N, 256>>>((const float*)pX2, (__nv_bfloat16*)pX2q,
                               (const unsigned*)psX2, H);

    // join: GEMM2 needs the W2 quant chain
    cudaStreamWaitEvent(0, evJ1, 0);

    dim3 g2(D / BNT, N / BMT);   // (16, 64)
    k_gemm<0><<<g2, 128, GEMM_SMEM>>>(
        (const __nv_bfloat16*)pX2q, (const __nv_bfloat16*)pW2q,
        (const float*)psX2, (const unsigned*)pa2, B2, out,
        nullptr, H, D);
}